// round 13
// baseline (speedup 1.0000x reference)
#include <cuda_runtime.h>
#include <cuda_bf16.h>
#include <cuda_fp16.h>
#include <cstdint>

#define BSZ 2
#define TSEQ 1024
#define DMODEL 1024
#define NH 8
#define HD 128
#define BT (BSZ * TSEQ)

// ===================== low-level helpers (sm_80+ instructions only) =====================
__device__ __forceinline__ uint32_t smem_u32(const void* p) {
    uint32_t a;
    asm("{ .reg .u64 t; cvta.to.shared.u64 t, %1; cvt.u32.u64 %0, t; }" : "=r"(a) : "l"(p));
    return a;
}
#define CP_ASYNC16(sm_addr, gptr) \
    asm volatile("cp.async.cg.shared.global [%0], [%1], 16;" :: "r"(sm_addr), "l"(gptr))
#define CP_COMMIT() asm volatile("cp.async.commit_group;")
#define CP_WAIT0()  asm volatile("cp.async.wait_group 0;")
#define CP_WAIT1()  asm volatile("cp.async.wait_group 1;")

__device__ __forceinline__ void ldm4(uint32_t* r, uint32_t a) {
    asm volatile("ldmatrix.sync.aligned.m8n8.x4.shared.b16 {%0,%1,%2,%3}, [%4];"
                 : "=r"(r[0]), "=r"(r[1]), "=r"(r[2]), "=r"(r[3]) : "r"(a));
}
__device__ __forceinline__ void ldm2(uint32_t* r, uint32_t a) {
    asm volatile("ldmatrix.sync.aligned.m8n8.x2.shared.b16 {%0,%1}, [%2];"
                 : "=r"(r[0]), "=r"(r[1]) : "r"(a));
}
__device__ __forceinline__ void mma_bf(float* c, const uint32_t* a, const uint32_t* b) {
    asm volatile(
        "mma.sync.aligned.m16n8k16.row.col.f32.bf16.bf16.f32 "
        "{%0,%1,%2,%3}, {%4,%5,%6,%7}, {%8,%9}, {%0,%1,%2,%3};"
        : "+f"(c[0]), "+f"(c[1]), "+f"(c[2]), "+f"(c[3])
        : "r"(a[0]), "r"(a[1]), "r"(a[2]), "r"(a[3]), "r"(b[0]), "r"(b[1]));
}
__device__ __forceinline__ void mma_fp(float* c, const uint32_t* a, const uint32_t* b) {
    asm volatile(
        "mma.sync.aligned.m16n8k16.row.col.f32.f16.f16.f32 "
        "{%0,%1,%2,%3}, {%4,%5,%6,%7}, {%8,%9}, {%0,%1,%2,%3};"
        : "+f"(c[0]), "+f"(c[1]), "+f"(c[2]), "+f"(c[3])
        : "r"(a[0]), "r"(a[1]), "r"(a[2]), "r"(a[3]), "r"(b[0]), "r"(b[1]));
}
template <int MMAT>
__device__ __forceinline__ void mma_any(float* c, const uint32_t* a, const uint32_t* b) {
    if constexpr (MMAT == 0) mma_bf(c, a, b);
    else mma_fp(c, a, b);
}
// tiles: rows of 64 b16 elems (128B) with 16B-granular XOR swizzle
__device__ __forceinline__ uint32_t swz(uint32_t base, int row, int kbytes) {
    uint32_t bo = (uint32_t)(row * 128 + kbytes);
    return base + (bo ^ ((bo >> 3) & 0x70));
}
template <int ROWS>
__device__ __forceinline__ void tile_cp_r(uint32_t sdst, const __nv_bfloat16* __restrict__ src,
                                          int rstride, int tid) {
#pragma unroll
    for (int it = 0; it < ROWS / 32; it++) {
        int f = tid + it * 256;
        int row = f >> 3, c8 = (f & 7) << 3;
        uint32_t bo = (uint32_t)(row * 128 + c8 * 2);
        uint32_t sw = bo ^ ((bo >> 3) & 0x70);
        CP_ASYNC16(sdst + sw, src + (size_t)row * rstride + c8);
    }
}
__device__ __forceinline__ void bsplit(float v, __nv_bfloat16& h, __nv_bfloat16& l) {
    h = __float2bfloat16(v);
    l = __float2bfloat16(v - __bfloat162float(h));
}
__device__ __forceinline__ uint32_t pack_bf2(__nv_bfloat16 a, __nv_bfloat16 b) {
    __nv_bfloat162 t; t.x = a; t.y = b;
    return *reinterpret_cast<uint32_t*>(&t);
}
__device__ __forceinline__ uint32_t pack_h2(__half a, __half b) {
    __half2 t; t.x = a; t.y = b;
    return *reinterpret_cast<uint32_t*>(&t);
}

// ===================== scratch offsets (2-byte elements) =====================
#define MEG 1048576LL
#define O_QRH (0LL)
#define O_QRL (2 * MEG)
#define O_KYH (4 * MEG)
#define O_KYL (6 * MEG)
#define O_VAH (8 * MEG)
#define O_VAL (10 * MEG)
#define O_WQH (12 * MEG)
#define O_WQL (20 * MEG)
#define O_WKH (28 * MEG)
#define O_WKL (36 * MEG)
#define O_WVH (44 * MEG)
#define O_WOH (45 * MEG)
#define O_WVL (52 * MEG)
#define O_WOL (53 * MEG)
#define O_QH  (64 * MEG)
#define O_QL  (80 * MEG)
#define O_KH  (96 * MEG)
#define O_KL  (112 * MEG)
#define O_VTH (128 * MEG)            // fp16 single Vt
#define O_PH  (132 * MEG)            // fp16 P (single)
#define O_HH  (148 * MEG)            // bf16 split head
#define O_HL  (150 * MEG)
#define O_PT  (152 * MEG)            // fp16 unnormalized exp: 8 planes x 16M
#define SCRATCH_ELEMS (280 * MEG)
__device__ __nv_bfloat16 g_bf[SCRATCH_ELEMS];
__device__ float g_inv[8 * BSZ * NH * TSEQ];   // 0.125/rowsum per (i, b, h, t)

#define PT_PLANE 16777216LL          // BSZ*NH*TSEQ*TSEQ per i

// ===================== fp32 -> bf16 hi/lo split, multi-source (8 elems/thread) =====================
__global__ __launch_bounds__(256) void cvt_m(
    const float* __restrict__ s0, const float* __restrict__ s1, const float* __restrict__ s2,
    __nv_bfloat16* __restrict__ base, long long zs, long long lo_off, int n8)
{
    int i = blockIdx.x * 256 + threadIdx.x;
    if (i >= n8) return;
    int z = blockIdx.y;
    const float* x = (z == 0) ? s0 : ((z == 1) ? s1 : s2);
    __nv_bfloat16* hi = base + (long long)z * zs;
    __nv_bfloat16* lo = hi + lo_off;
    float4 v0 = reinterpret_cast<const float4*>(x)[2 * i];
    float4 v1 = reinterpret_cast<const float4*>(x)[2 * i + 1];
    __nv_bfloat16 h[8], l[8];
    bsplit(v0.x, h[0], l[0]); bsplit(v0.y, h[1], l[1]);
    bsplit(v0.z, h[2], l[2]); bsplit(v0.w, h[3], l[3]);
    bsplit(v1.x, h[4], l[4]); bsplit(v1.y, h[5], l[5]);
    bsplit(v1.z, h[6], l[6]); bsplit(v1.w, h[7], l[7]);
    reinterpret_cast<uint4*>(hi)[i] = make_uint4(pack_bf2(h[0], h[1]), pack_bf2(h[2], h[3]),
                                                 pack_bf2(h[4], h[5]), pack_bf2(h[6], h[7]));
    reinterpret_cast<uint4*>(lo)[i] = make_uint4(pack_bf2(l[0], l[1]), pack_bf2(l[2], l[3]),
                                                 pack_bf2(l[4], l[5]), pack_bf2(l[6], l[7]));
}

// ===================== templated GEMM: C = A @ B^T =====================
// SPLITA/SPLITB: hi/lo operand splits. passes = 1 + SPLITA + SPLITB
// modes: 0 = fp32 C; 1 = bf16-split C; 2 = fp16 single transposed C; 3 = per-z (z<16: 1, else 2)
#define G_SMEM 98304    // 2 stages x 48KB (64x128 tile) -> 2 CTAs/SM
#define H_SMEM 98304

template <int MMAT, int SPLITA, int SPLITB, int WM, int WN, int MT, int NT, int NS>
__global__ __launch_bounds__(256) void gemm_bx3(
    const __nv_bfloat16* __restrict__ Ahi, const __nv_bfloat16* __restrict__ Alo,
    const __nv_bfloat16* __restrict__ Bhi, const __nv_bfloat16* __restrict__ Blo,
    float* __restrict__ Cf, __nv_bfloat16* __restrict__ Chi, __nv_bfloat16* __restrict__ Clo,
    int kchunks, int lda, int ldb, int ldc, int zdiv,
    long long sA1, long long sA2, long long sB1, long long sB2,
    long long sC1, long long sC2, int mode)
{
    constexpr int M_TILE = WM * MT * 16;
    constexpr int N_TILE = WN * NT * 8;
    constexpr int SA = M_TILE * 128;
    constexpr int SB = N_TILE * 128;
    constexpr int NA = SPLITA ? 2 : 1;
    constexpr int NB = SPLITB ? 2 : 1;
    constexpr int STAGE = NA * SA + NB * SB;

    extern __shared__ __align__(1024) char sm[];
    int tid = threadIdx.x, wid = tid >> 5, l = tid & 31;
    int wm = wid / WN, wn = wid % WN;
    uint32_t sb = smem_u32(sm);

    int md = (mode == 3) ? ((blockIdx.z < 16) ? 1 : 2) : mode;

    long long zq = blockIdx.z / zdiv, zr = blockIdx.z % zdiv;
    const __nv_bfloat16* A0 = Ahi + zq * sA1 + zr * sA2 + (long long)blockIdx.y * M_TILE * lda;
    const __nv_bfloat16* A1 = Alo + zq * sA1 + zr * sA2 + (long long)blockIdx.y * M_TILE * lda;
    const __nv_bfloat16* B0 = Bhi + zq * sB1 + zr * sB2 + (long long)blockIdx.x * N_TILE * ldb;
    const __nv_bfloat16* B1 = Blo + zq * sB1 + zr * sB2 + (long long)blockIdx.x * N_TILE * ldb;

    float c[MT][NT][4];
#pragma unroll
    for (int a = 0; a < MT; a++)
#pragma unroll
        for (int b2 = 0; b2 < NT; b2++)
#pragma unroll
            for (int d = 0; d < 4; d++) c[a][b2][d] = 0.f;

    auto load_chunk = [&](int ck) {
        uint32_t bo = sb + (ck % NS) * STAGE;
        tile_cp_r<M_TILE>(bo, A0 + ck * 64, lda, tid);
        if constexpr (SPLITA)
            tile_cp_r<M_TILE>(bo + SA, A1 + ck * 64, lda, tid);
        tile_cp_r<N_TILE>(bo + NA * SA, B0 + ck * 64, ldb, tid);
        if constexpr (SPLITB)
            tile_cp_r<N_TILE>(bo + NA * SA + SB, B1 + ck * 64, ldb, tid);
        CP_COMMIT();
    };
#pragma unroll
    for (int p = 0; p < NS - 1; p++)
        if (p < kchunks) load_chunk(p);

    for (int ck = 0; ck < kchunks; ck++) {
        if constexpr (NS == 3) {
            if (ck + 1 < kchunks) CP_WAIT1();
            else CP_WAIT0();
        } else {
            CP_WAIT0();
        }
        __syncthreads();
        if (ck + NS - 1 < kchunks) load_chunk(ck + NS - 1);
        uint32_t bo = sb + (ck % NS) * STAGE;
#pragma unroll
        for (int s16 = 0; s16 < 4; s16++) {
            int kb = s16 * 16;
            uint32_t bh[NT][2], bl[NT][2];
#pragma unroll
            for (int nt = 0; nt < NT; nt++) {
                uint32_t ad = swz(bo + NA * SA, wn * (NT * 8) + nt * 8 + (l & 7),
                                  (kb + ((l >> 3) & 1) * 8) * 2);
                ldm2(bh[nt], ad);
                if constexpr (SPLITB) ldm2(bl[nt], ad + SB);
            }
#pragma unroll
            for (int mt = 0; mt < MT; mt++) {
                uint32_t ah[4], al[4];
                uint32_t aa = swz(bo, wm * (MT * 16) + mt * 16 + (l & 15),
                                  (kb + ((l >> 4) & 1) * 8) * 2);
                ldm4(ah, aa);
                if constexpr (SPLITA) ldm4(al, aa + SA);
#pragma unroll
                for (int nt = 0; nt < NT; nt++) {
                    mma_any<MMAT>(c[mt][nt], ah, bh[nt]);
                    if constexpr (SPLITB) mma_any<MMAT>(c[mt][nt], ah, bl[nt]);
                    if constexpr (SPLITA) mma_any<MMAT>(c[mt][nt], al, bh[nt]);
                }
            }
        }
    }

    // epilogue
    int g = l >> 2, q2 = (l & 3) * 2;
    long long czb = zq * sC1 + zr * sC2;
#pragma unroll
    for (int mt = 0; mt < MT; mt++) {
        long long m0 = (long long)blockIdx.y * M_TILE + wm * (MT * 16) + mt * 16 + g;
        long long m1 = m0 + 8;
#pragma unroll
        for (int nt = 0; nt < NT; nt++) {
            int n0 = blockIdx.x * N_TILE + wn * (NT * 8) + nt * 8 + q2;
            float* cc = c[mt][nt];
            if (md == 0) {
                *reinterpret_cast<float2*>(Cf + czb + m0 * ldc + n0) = make_float2(cc[0], cc[1]);
                *reinterpret_cast<float2*>(Cf + czb + m1 * ldc + n0) = make_float2(cc[2], cc[3]);
            } else if (md == 1) {
                __nv_bfloat16 h0, l0, h1, l1;
                bsplit(cc[0], h0, l0); bsplit(cc[1], h1, l1);
                *reinterpret_cast<uint32_t*>(Chi + czb + m0 * ldc + n0) = pack_bf2(h0, h1);
                *reinterpret_cast<uint32_t*>(Clo + czb + m0 * ldc + n0) = pack_bf2(l0, l1);
                bsplit(cc[2], h0, l0); bsplit(cc[3], h1, l1);
                *reinterpret_cast<uint32_t*>(Chi + czb + m1 * ldc + n0) = pack_bf2(h0, h1);
                *reinterpret_cast<uint32_t*>(Clo + czb + m1 * ldc + n0) = pack_bf2(l0, l1);
            } else {
                __half* ChiH = reinterpret_cast<__half*>(Chi + czb);
#pragma unroll
                for (int half = 0; half < 2; half++) {
                    long long m = half ? m1 : m0;
                    int bb = (int)(m >> 10), ss = (int)(m & 1023);
                    long long base = (long long)bb * DMODEL * TSEQ + ss;
#pragma unroll
                    for (int j = 0; j < 2; j++)
                        ChiH[base + (long long)(n0 + j) * TSEQ] = __float2half_rn(cc[half * 2 + j]);
                }
            }
        }
    }
}

// ===================== attention score pass (per-i CTAs; row-sums in registers) =====================
#define AQ_BUF    0        // 64KB: Qh kh0|kh1, Ql kh0|kh1
#define AK_BUF    65536    // 2 x 32KB K double buffer
#define AS_RSPART 131072   // 128*4 fp32
#define AS_SMEM   133632

__global__ __launch_bounds__(256) void attn_score(
    const __nv_bfloat16* __restrict__ Qh, const __nv_bfloat16* __restrict__ Ql,
    const __nv_bfloat16* __restrict__ Kh, const __nv_bfloat16* __restrict__ Kl,
    __half* __restrict__ PT, float* __restrict__ inv_out)
{
    extern __shared__ __align__(1024) char sm[];
    int tid = threadIdx.x, wid = tid >> 5, l = tid & 31;
    int wm = wid >> 2, wn = wid & 3;
    uint32_t sb = smem_u32(sm);
    float* rspart = reinterpret_cast<float*>(sm + AS_RSPART);

    int i = blockIdx.y;
    int z = blockIdx.z, b = z >> 3, h = z & 7;
    int t0 = blockIdx.x * 128;
    const float SC = 0.08838834764831845f;   // 1/sqrt(128)
    int g = l >> 2, q2 = (l & 3) * 2;

    float c[4][4][4];
#pragma unroll
    for (int a = 0; a < 4; a++)
#pragma unroll
        for (int b2 = 0; b2 < 4; b2++)
#pragma unroll
            for (int d = 0; d < 4; d++) c[a][b2][d] = 0.f;
    float ps[8];
#pragma unroll
    for (int k = 0; k < 8; k++) ps[k] = 0.f;

    {
        size_t qbase = ((size_t)(i * BSZ + b) * TSEQ + t0) * DMODEL + h * HD;
#pragma unroll
        for (int kh = 0; kh < 2; kh++) {
            tile_cp_r<128>(sb + AQ_BUF + kh * 16384,         Qh + qbase + kh * 64, DMODEL, tid);
            tile_cp_r<128>(sb + AQ_BUF + 32768 + kh * 16384, Ql + qbase + kh * 64, DMODEL, tid);
        }
        CP_COMMIT();
    }
    auto stage_load = [&](int s) {
        int kh = s & 1, ch = s >> 1;
        size_t kb = ((size_t)(i * BSZ + b) * TSEQ + ch * 128) * DMODEL + h * HD + kh * 64;
        uint32_t ko = sb + AK_BUF + (s & 1) * 32768;
        tile_cp_r<128>(ko,         Kh + kb, DMODEL, tid);
        tile_cp_r<128>(ko + 16384, Kl + kb, DMODEL, tid);
        CP_COMMIT();
    };
    stage_load(0);

    size_t bh_el = ((size_t)(b * NH + h)) << 20;
    size_t rowbase = (size_t)i * PT_PLANE + bh_el + ((size_t)t0 << 10);
    const int S = 16;

    for (int s = 0; s < S; s++) {
        CP_WAIT0();
        __syncthreads();
        if (s + 1 < S) stage_load(s + 1);
        int kh = s & 1, ch = s >> 1;
        uint32_t qo = sb + AQ_BUF + kh * 16384;
        uint32_t ko = sb + AK_BUF + (s & 1) * 32768;
#pragma unroll
        for (int s16 = 0; s16 < 4; s16++) {
            int kb = s16 * 16;
            uint32_t bhf[4][2], blf[4][2];
#pragma unroll
            for (int nt = 0; nt < 4; nt++) {
                uint32_t ad = swz(ko, wn * 32 + nt * 8 + (l & 7),
                                  (kb + ((l >> 3) & 1) * 8) * 2);
                ldm2(bhf[nt], ad);
                ldm2(blf[nt], ad + 16384);
            }
#pragma unroll
            for (int mt = 0; mt < 4; mt++) {
                uint32_t ah[4], al[4];
                uint32_t aa = swz(qo, wm * 64 + mt * 16 + (l & 15),
                                  (kb + ((l >> 4) & 1) * 8) * 2);
                ldm4(ah, aa);
                ldm4(al, aa + 32768);
#pragma unroll
                for (int nt = 0; nt < 4; nt++) {
                    mma_bf(c[mt][nt], ah, bhf[nt]);
                    mma_bf(c[mt][nt], ah, blf[nt]);
                    mma_bf(c[mt][nt], al, bhf[nt]);
                }
            }
        }
        if (kh == 1) {
#pragma unroll
            for (int mt = 0; mt < 4; mt++) {
                int r0 = wm * 64 + mt * 16 + g, r1 = r0 + 8;
                float s0 = 0.f, s1 = 0.f;
#pragma unroll
                for (int nt = 0; nt < 4; nt++) {
                    int col = ch * 128 + wn * 32 + nt * 8 + q2;
                    float e0 = __expf(c[mt][nt][0] * SC);
                    float e1 = __expf(c[mt][nt][1] * SC);
                    float e2 = __expf(c[mt][nt][2] * SC);
                    float e3 = __expf(c[mt][nt][3] * SC);
                    s0 += e0 + e1; s1 += e2 + e3;
                    *reinterpret_cast<uint32_t*>(PT + rowbase + ((size_t)r0 << 10) + col) =
                        pack_h2(__float2half_rn(e0), __float2half_rn(e1));
                    *reinterpret_cast<uint32_t*>(PT + rowbase + ((size_t)r1 << 10) + col) =
                        pack_h2(__float2half_rn(e2), __float2half_rn(e3));
                }
                ps[2 * mt] += s0; ps[2 * mt + 1] += s1;
            }
#pragma unroll
            for (int a = 0; a < 4; a++)
#pragma unroll
                for (int b2 = 0; b2 < 4; b2++)
#pragma unroll
                    for (int d = 0; d < 4; d++) c[a][b2][d] = 0.f;
        }
    }

#pragma unroll
    for (int off = 1; off <= 2; off <<= 1)
#pragma unroll
        for (int k = 0; k < 8; k++)
            ps[k] += __shfl_xor_sync(0xffffffffu, ps[k], off);
    if ((l & 3) == 0) {
#pragma unroll
        for (int mt = 0; mt < 4; mt++) {
            int r0 = wm * 64 + mt * 16 + g;
            rspart[r0 * 4 + wn] = ps[2 * mt];
            rspart[(r0 + 8) * 4 + wn] = ps[2 * mt + 1];
        }
    }
    __syncthreads();
    if (tid < 128) {
        float sum = rspart[tid * 4] + rspart[tid * 4 + 1] +
                    rspart[tid * 4 + 2] + rspart[tid * 4 + 3];
        inv_out[i * (BSZ * NH * TSEQ) + (b * NH + h) * TSEQ + t0 + tid] = 0.125f / sum;
    }
}

// ===================== normalize + mean over i (vectorized 16B; P single fp16) =====================
__global__ __launch_bounds__(256) void attn_norm(
    const __half* __restrict__ PT, const float* __restrict__ inv,
    float* __restrict__ attn_out, __half* __restrict__ Ph)
{
    int r = blockIdx.x * 2 + (threadIdx.x >> 7);
    int c8 = (threadIdx.x & 127) * 8;
    size_t rowoff = ((size_t)r << 10) + c8;
    float acc[8] = {};
#pragma unroll
    for (int i = 0; i < 8; i++) {
        float iv = inv[i * (BSZ * NH * TSEQ) + r];
        uint4 hv = *reinterpret_cast<const uint4*>(PT + (size_t)i * PT_PLANE + rowoff);
        __half2* hp = reinterpret_cast<__half2*>(&hv);
#pragma unroll
        for (int j = 0; j < 4; j++) {
            float2 f = __half22float2(hp[j]);
            acc[2 * j]     += f.x * iv;
            acc[2 * j + 1] += f.y * iv;
        }
    }
    float4* ao = reinterpret_cast<float4*>(attn_out + rowoff);
    ao[0] = make_float4(acc[0], acc[1], acc[2], acc[3]);
    ao[1] = make_float4(acc[4], acc[5], acc[6], acc[7]);
    uint4 ph;
    ph.x = pack_h2(__float2half_rn(acc[0]), __float2half_rn(acc[1]));
    ph.y = pack_h2(__float2half_rn(acc[2]), __float2half_rn(acc[3]));
    ph.z = pack_h2(__float2half_rn(acc[4]), __float2half_rn(acc[5]));
    ph.w = pack_h2(__float2half_rn(acc[6]), __float2half_rn(acc[7]));
    *reinterpret_cast<uint4*>(Ph + rowoff) = ph;
}

// ===================== host =====================
extern "C" void kernel_launch(void* const* d_in, const int* in_sizes, int n_in,
                              void* d_out, int out_size) {
    (void)in_sizes; (void)n_in; (void)out_size;
    const float* query = (const float*)d_in[0];
    const float* key   = (const float*)d_in[1];
    const float* value = (const float*)d_in[2];
    const float* Wq    = (const float*)d_in[3];
    const float* Wk    = (const float*)d_in[4];
    const float* Wv    = (const float*)d_in[5];
    const float* Wo    = (const float*)d_in[6];
    float* out = (float*)d_out;
    float* out_attn = out + (size_t)BT * DMODEL;

    __nv_bfloat16* S;
    cudaGetSymbolAddress((void**)&S, g_bf);
    float* pInv;
    cudaGetSymbolAddress((void**)&pInv, g_inv);
#define AT(o) (S + (size_t)(o))
#define ATH(o) (reinterpret_cast<__half*>(S + (size_t)(o)))

    // kGen: 64x128 tile, 2 stages, 96KB smem -> 2 CTAs/SM
    auto* kGen  = gemm_bx3<0, 1, 1, 2, 4, 2, 4, 2>;
    auto* kHead = gemm_bx3<1, 0, 0, 2, 4, 4, 4, 3>;
    cudaFuncSetAttribute(kGen,  cudaFuncAttributeMaxDynamicSharedMemorySize, G_SMEM);
    cudaFuncSetAttribute(kHead, cudaFuncAttributeMaxDynamicSharedMemorySize, H_SMEM);
    cudaFuncSetAttribute(attn_score, cudaFuncAttributeMaxDynamicSharedMemorySize, AS_SMEM);

    dim3 blk(256);
    // 1-3: splits
    cvt_m<<<dim3(1024, 3), blk>>>(query, key, value, AT(O_QRH), 4 * MEG, 2 * MEG, 262144);
    cvt_m<<<dim3(4096, 2), blk>>>(Wq, Wk, Wq,        AT(O_WQH), 16 * MEG, 8 * MEG, 1048576);
    cvt_m<<<dim3(512, 1), blk>>>(Wv, Wv, Wv,         AT(O_WVH), 1 * MEG, 8 * MEG, 131072);

    // 4: merged Q + K + Vt projections (64x128 tiles, y=32)
    kGen<<<dim3(8, 32, 17), blk, G_SMEM>>>(
        AT(O_QRH), AT(O_QRL), AT(O_WQH), AT(O_WQL), nullptr, AT(O_QH), AT(O_QL),
        16, DMODEL, DMODEL, DMODEL, 8,
        4 * MEG, 0LL,
        16 * MEG, (long long)DMODEL * DMODEL,
        32 * MEG, (long long)BT * DMODEL, 3);

    // 5: Wo split
    cvt_m<<<dim3(512, 1), blk>>>(Wo, Wo, Wo, AT(O_WOH), 1 * MEG, 8 * MEG, 131072);

    // 6 (profiled): scores
    attn_score<<<dim3(TSEQ / 128, NH, BSZ * NH), blk, AS_SMEM>>>(
        AT(O_QH), AT(O_QL), AT(O_KH), AT(O_KL), ATH(O_PT), pInv);

    // 7: normalize + mean over i
    attn_norm<<<BSZ * NH * TSEQ / 2, blk>>>(
        ATH(O_PT), pInv, out_attn, ATH(O_PH));

    // 8: head = P @ Vt^T (pure fp16, 1 pass)
    kHead<<<dim3(1, 8, 16), blk, H_SMEM>>>(
        AT(O_PH), AT(O_PH), AT(O_VTH), AT(O_VTH), nullptr, AT(O_HH), AT(O_HL),
        16, TSEQ, TSEQ, DMODEL, 8,
        (long long)NH * TSEQ * TSEQ, (long long)TSEQ * TSEQ,
        (long long)DMODEL * TSEQ, (long long)HD * TSEQ,
        (long long)TSEQ * DMODEL, (long long)HD, 1);

    // 9: outputs = head @ Wo^T (fp32, 64x128 tiles, y=32)
    kGen<<<dim3(8, 32, 1), blk, G_SMEM>>>(
        AT(O_HH), AT(O_HL), AT(O_WOH), AT(O_WOL), out, nullptr, nullptr,
        16, DMODEL, DMODEL, DMODEL, 1, 0LL, 0LL, 0LL, 0LL, 0LL, 0LL, 0);
}

// round 14
// speedup vs baseline: 1.0309x; 1.0309x over previous
#include <cuda_runtime.h>
#include <cuda_bf16.h>
#include <cuda_fp16.h>
#include <cstdint>

#define BSZ 2
#define TSEQ 1024
#define DMODEL 1024
#define NH 8
#define HD 128
#define BT (BSZ * TSEQ)

// ===================== low-level helpers (sm_80+ instructions only) =====================
__device__ __forceinline__ uint32_t smem_u32(const void* p) {
    uint32_t a;
    asm("{ .reg .u64 t; cvta.to.shared.u64 t, %1; cvt.u32.u64 %0, t; }" : "=r"(a) : "l"(p));
    return a;
}
#define CP_ASYNC16(sm_addr, gptr) \
    asm volatile("cp.async.cg.shared.global [%0], [%1], 16;" :: "r"(sm_addr), "l"(gptr))
#define CP_COMMIT() asm volatile("cp.async.commit_group;")
#define CP_WAIT0()  asm volatile("cp.async.wait_group 0;")
#define CP_WAIT1()  asm volatile("cp.async.wait_group 1;")

__device__ __forceinline__ void ldm4(uint32_t* r, uint32_t a) {
    asm volatile("ldmatrix.sync.aligned.m8n8.x4.shared.b16 {%0,%1,%2,%3}, [%4];"
                 : "=r"(r[0]), "=r"(r[1]), "=r"(r[2]), "=r"(r[3]) : "r"(a));
}
__device__ __forceinline__ void ldm2(uint32_t* r, uint32_t a) {
    asm volatile("ldmatrix.sync.aligned.m8n8.x2.shared.b16 {%0,%1}, [%2];"
                 : "=r"(r[0]), "=r"(r[1]) : "r"(a));
}
__device__ __forceinline__ void mma_bf(float* c, const uint32_t* a, const uint32_t* b) {
    asm volatile(
        "mma.sync.aligned.m16n8k16.row.col.f32.bf16.bf16.f32 "
        "{%0,%1,%2,%3}, {%4,%5,%6,%7}, {%8,%9}, {%0,%1,%2,%3};"
        : "+f"(c[0]), "+f"(c[1]), "+f"(c[2]), "+f"(c[3])
        : "r"(a[0]), "r"(a[1]), "r"(a[2]), "r"(a[3]), "r"(b[0]), "r"(b[1]));
}
__device__ __forceinline__ void mma_fp(float* c, const uint32_t* a, const uint32_t* b) {
    asm volatile(
        "mma.sync.aligned.m16n8k16.row.col.f32.f16.f16.f32 "
        "{%0,%1,%2,%3}, {%4,%5,%6,%7}, {%8,%9}, {%0,%1,%2,%3};"
        : "+f"(c[0]), "+f"(c[1]), "+f"(c[2]), "+f"(c[3])
        : "r"(a[0]), "r"(a[1]), "r"(a[2]), "r"(a[3]), "r"(b[0]), "r"(b[1]));
}
template <int MMAT>
__device__ __forceinline__ void mma_any(float* c, const uint32_t* a, const uint32_t* b) {
    if constexpr (MMAT == 0) mma_bf(c, a, b);
    else mma_fp(c, a, b);
}
// tiles: rows of 64 b16 elems (128B) with 16B-granular XOR swizzle
__device__ __forceinline__ uint32_t swz(uint32_t base, int row, int kbytes) {
    uint32_t bo = (uint32_t)(row * 128 + kbytes);
    return base + (bo ^ ((bo >> 3) & 0x70));
}
template <int ROWS>
__device__ __forceinline__ void tile_cp_r(uint32_t sdst, const __nv_bfloat16* __restrict__ src,
                                          int rstride, int tid) {
#pragma unroll
    for (int it = 0; it < ROWS / 32; it++) {
        int f = tid + it * 256;
        int row = f >> 3, c8 = (f & 7) << 3;
        uint32_t bo = (uint32_t)(row * 128 + c8 * 2);
        uint32_t sw = bo ^ ((bo >> 3) & 0x70);
        CP_ASYNC16(sdst + sw, src + (size_t)row * rstride + c8);
    }
}
__device__ __forceinline__ void bsplit(float v, __nv_bfloat16& h, __nv_bfloat16& l) {
    h = __float2bfloat16(v);
    l = __float2bfloat16(v - __bfloat162float(h));
}
__device__ __forceinline__ uint32_t pack_bf2(__nv_bfloat16 a, __nv_bfloat16 b) {
    __nv_bfloat162 t; t.x = a; t.y = b;
    return *reinterpret_cast<uint32_t*>(&t);
}
__device__ __forceinline__ uint32_t pack_h2(__half a, __half b) {
    __half2 t; t.x = a; t.y = b;
    return *reinterpret_cast<uint32_t*>(&t);
}

// ===================== scratch offsets (2-byte elements) =====================
#define MEG 1048576LL
#define O_QRH (0LL)
#define O_QRL (2 * MEG)
#define O_KYH (4 * MEG)
#define O_KYL (6 * MEG)
#define O_VAH (8 * MEG)
#define O_VAL (10 * MEG)
#define O_WQH (12 * MEG)
#define O_WQL (20 * MEG)
#define O_WKH (28 * MEG)
#define O_WKL (36 * MEG)
#define O_WVH (44 * MEG)
#define O_WOH (45 * MEG)
#define O_WVL (52 * MEG)
#define O_WOL (53 * MEG)
#define O_QH  (64 * MEG)
#define O_QL  (80 * MEG)
#define O_KH  (96 * MEG)
#define O_KL  (112 * MEG)
#define O_VTH (128 * MEG)            // fp16 single Vt
#define O_PH  (132 * MEG)            // fp16 P (single)
#define O_HH  (148 * MEG)            // bf16 split head
#define O_HL  (150 * MEG)
#define O_PT  (152 * MEG)            // fp16 unnormalized exp: 8 planes x 16M
#define SCRATCH_ELEMS (280 * MEG)
__device__ __nv_bfloat16 g_bf[SCRATCH_ELEMS];
__device__ float g_inv[8 * BSZ * NH * TSEQ];   // 0.125/rowsum per (i, b, h, t)

#define PT_PLANE 16777216LL          // BSZ*NH*TSEQ*TSEQ per i

// ===================== fp32 -> bf16 hi/lo split, multi-source (8 elems/thread) =====================
__global__ __launch_bounds__(256) void cvt_m(
    const float* __restrict__ s0, const float* __restrict__ s1, const float* __restrict__ s2,
    __nv_bfloat16* __restrict__ base, long long zs, long long lo_off, int n8)
{
    int i = blockIdx.x * 256 + threadIdx.x;
    if (i >= n8) return;
    int z = blockIdx.y;
    const float* x = (z == 0) ? s0 : ((z == 1) ? s1 : s2);
    __nv_bfloat16* hi = base + (long long)z * zs;
    __nv_bfloat16* lo = hi + lo_off;
    float4 v0 = reinterpret_cast<const float4*>(x)[2 * i];
    float4 v1 = reinterpret_cast<const float4*>(x)[2 * i + 1];
    __nv_bfloat16 h[8], l[8];
    bsplit(v0.x, h[0], l[0]); bsplit(v0.y, h[1], l[1]);
    bsplit(v0.z, h[2], l[2]); bsplit(v0.w, h[3], l[3]);
    bsplit(v1.x, h[4], l[4]); bsplit(v1.y, h[5], l[5]);
    bsplit(v1.z, h[6], l[6]); bsplit(v1.w, h[7], l[7]);
    reinterpret_cast<uint4*>(hi)[i] = make_uint4(pack_bf2(h[0], h[1]), pack_bf2(h[2], h[3]),
                                                 pack_bf2(h[4], h[5]), pack_bf2(h[6], h[7]));
    reinterpret_cast<uint4*>(lo)[i] = make_uint4(pack_bf2(l[0], l[1]), pack_bf2(l[2], l[3]),
                                                 pack_bf2(l[4], l[5]), pack_bf2(l[6], l[7]));
}

// ===================== templated GEMM: C = A @ B^T =====================
// SPLITA/SPLITB: hi/lo operand splits. passes = 1 + SPLITA + SPLITB
// modes: 0 = fp32 C; 1 = bf16-split C; 2 = fp16 single transposed C; 3 = per-z (z<16: 1, else 2)
#define GP_SMEM 98304   // proj: 2 stages x 48KB (64x128) -> 2 CTAs/SM
#define GO_SMEM 196608  // out:  3 stages x 64KB (128x128)
#define H_SMEM  98304

template <int MMAT, int SPLITA, int SPLITB, int WM, int WN, int MT, int NT, int NS>
__global__ __launch_bounds__(256) void gemm_bx3(
    const __nv_bfloat16* __restrict__ Ahi, const __nv_bfloat16* __restrict__ Alo,
    const __nv_bfloat16* __restrict__ Bhi, const __nv_bfloat16* __restrict__ Blo,
    float* __restrict__ Cf, __nv_bfloat16* __restrict__ Chi, __nv_bfloat16* __restrict__ Clo,
    int kchunks, int lda, int ldb, int ldc, int zdiv,
    long long sA1, long long sA2, long long sB1, long long sB2,
    long long sC1, long long sC2, int mode)
{
    constexpr int M_TILE = WM * MT * 16;
    constexpr int N_TILE = WN * NT * 8;
    constexpr int SA = M_TILE * 128;
    constexpr int SB = N_TILE * 128;
    constexpr int NA = SPLITA ? 2 : 1;
    constexpr int NB = SPLITB ? 2 : 1;
    constexpr int STAGE = NA * SA + NB * SB;

    extern __shared__ __align__(1024) char sm[];
    int tid = threadIdx.x, wid = tid >> 5, l = tid & 31;
    int wm = wid / WN, wn = wid % WN;
    uint32_t sb = smem_u32(sm);

    int md = (mode == 3) ? ((blockIdx.z < 16) ? 1 : 2) : mode;

    long long zq = blockIdx.z / zdiv, zr = blockIdx.z % zdiv;
    const __nv_bfloat16* A0 = Ahi + zq * sA1 + zr * sA2 + (long long)blockIdx.y * M_TILE * lda;
    const __nv_bfloat16* A1 = Alo + zq * sA1 + zr * sA2 + (long long)blockIdx.y * M_TILE * lda;
    const __nv_bfloat16* B0 = Bhi + zq * sB1 + zr * sB2 + (long long)blockIdx.x * N_TILE * ldb;
    const __nv_bfloat16* B1 = Blo + zq * sB1 + zr * sB2 + (long long)blockIdx.x * N_TILE * ldb;

    float c[MT][NT][4];
#pragma unroll
    for (int a = 0; a < MT; a++)
#pragma unroll
        for (int b2 = 0; b2 < NT; b2++)
#pragma unroll
            for (int d = 0; d < 4; d++) c[a][b2][d] = 0.f;

    auto load_chunk = [&](int ck) {
        uint32_t bo = sb + (ck % NS) * STAGE;
        tile_cp_r<M_TILE>(bo, A0 + ck * 64, lda, tid);
        if constexpr (SPLITA)
            tile_cp_r<M_TILE>(bo + SA, A1 + ck * 64, lda, tid);
        tile_cp_r<N_TILE>(bo + NA * SA, B0 + ck * 64, ldb, tid);
        if constexpr (SPLITB)
            tile_cp_r<N_TILE>(bo + NA * SA + SB, B1 + ck * 64, ldb, tid);
        CP_COMMIT();
    };
#pragma unroll
    for (int p = 0; p < NS - 1; p++)
        if (p < kchunks) load_chunk(p);

    for (int ck = 0; ck < kchunks; ck++) {
        if constexpr (NS == 3) {
            if (ck + 1 < kchunks) CP_WAIT1();
            else CP_WAIT0();
        } else {
            CP_WAIT0();
        }
        __syncthreads();
        if (ck + NS - 1 < kchunks) load_chunk(ck + NS - 1);
        uint32_t bo = sb + (ck % NS) * STAGE;
#pragma unroll
        for (int s16 = 0; s16 < 4; s16++) {
            int kb = s16 * 16;
            uint32_t bh[NT][2], bl[NT][2];
#pragma unroll
            for (int nt = 0; nt < NT; nt++) {
                uint32_t ad = swz(bo + NA * SA, wn * (NT * 8) + nt * 8 + (l & 7),
                                  (kb + ((l >> 3) & 1) * 8) * 2);
                ldm2(bh[nt], ad);
                if constexpr (SPLITB) ldm2(bl[nt], ad + SB);
            }
#pragma unroll
            for (int mt = 0; mt < MT; mt++) {
                uint32_t ah[4], al[4];
                uint32_t aa = swz(bo, wm * (MT * 16) + mt * 16 + (l & 15),
                                  (kb + ((l >> 4) & 1) * 8) * 2);
                ldm4(ah, aa);
                if constexpr (SPLITA) ldm4(al, aa + SA);
#pragma unroll
                for (int nt = 0; nt < NT; nt++) {
                    mma_any<MMAT>(c[mt][nt], ah, bh[nt]);
                    if constexpr (SPLITB) mma_any<MMAT>(c[mt][nt], ah, bl[nt]);
                    if constexpr (SPLITA) mma_any<MMAT>(c[mt][nt], al, bh[nt]);
                }
            }
        }
    }

    // epilogue
    int g = l >> 2, q2 = (l & 3) * 2;
    long long czb = zq * sC1 + zr * sC2;
#pragma unroll
    for (int mt = 0; mt < MT; mt++) {
        long long m0 = (long long)blockIdx.y * M_TILE + wm * (MT * 16) + mt * 16 + g;
        long long m1 = m0 + 8;
#pragma unroll
        for (int nt = 0; nt < NT; nt++) {
            int n0 = blockIdx.x * N_TILE + wn * (NT * 8) + nt * 8 + q2;
            float* cc = c[mt][nt];
            if (md == 0) {
                *reinterpret_cast<float2*>(Cf + czb + m0 * ldc + n0) = make_float2(cc[0], cc[1]);
                *reinterpret_cast<float2*>(Cf + czb + m1 * ldc + n0) = make_float2(cc[2], cc[3]);
            } else if (md == 1) {
                __nv_bfloat16 h0, l0, h1, l1;
                bsplit(cc[0], h0, l0); bsplit(cc[1], h1, l1);
                *reinterpret_cast<uint32_t*>(Chi + czb + m0 * ldc + n0) = pack_bf2(h0, h1);
                *reinterpret_cast<uint32_t*>(Clo + czb + m0 * ldc + n0) = pack_bf2(l0, l1);
                bsplit(cc[2], h0, l0); bsplit(cc[3], h1, l1);
                *reinterpret_cast<uint32_t*>(Chi + czb + m1 * ldc + n0) = pack_bf2(h0, h1);
                *reinterpret_cast<uint32_t*>(Clo + czb + m1 * ldc + n0) = pack_bf2(l0, l1);
            } else {
                __half* ChiH = reinterpret_cast<__half*>(Chi + czb);
#pragma unroll
                for (int half = 0; half < 2; half++) {
                    long long m = half ? m1 : m0;
                    int bb = (int)(m >> 10), ss = (int)(m & 1023);
                    long long base = (long long)bb * DMODEL * TSEQ + ss;
#pragma unroll
                    for (int j = 0; j < 2; j++)
                        ChiH[base + (long long)(n0 + j) * TSEQ] = __float2half_rn(cc[half * 2 + j]);
                }
            }
        }
    }
}

// ===================== attention score pass (per-i CTAs; row-sums in registers) =====================
#define AQ_BUF    0        // 64KB: Qh kh0|kh1, Ql kh0|kh1
#define AK_BUF    65536    // 2 x 32KB K double buffer
#define AS_RSPART 131072   // 128*4 fp32
#define AS_SMEM   133632

__global__ __launch_bounds__(256) void attn_score(
    const __nv_bfloat16* __restrict__ Qh, const __nv_bfloat16* __restrict__ Ql,
    const __nv_bfloat16* __restrict__ Kh, const __nv_bfloat16* __restrict__ Kl,
    __half* __restrict__ PT, float* __restrict__ inv_out)
{
    extern __shared__ __align__(1024) char sm[];
    int tid = threadIdx.x, wid = tid >> 5, l = tid & 31;
    int wm = wid >> 2, wn = wid & 3;
    uint32_t sb = smem_u32(sm);
    float* rspart = reinterpret_cast<float*>(sm + AS_RSPART);

    int i = blockIdx.y;
    int z = blockIdx.z, b = z >> 3, h = z & 7;
    int t0 = blockIdx.x * 128;
    const float SC = 0.08838834764831845f;   // 1/sqrt(128)
    int g = l >> 2, q2 = (l & 3) * 2;

    float c[4][4][4];
#pragma unroll
    for (int a = 0; a < 4; a++)
#pragma unroll
        for (int b2 = 0; b2 < 4; b2++)
#pragma unroll
            for (int d = 0; d < 4; d++) c[a][b2][d] = 0.f;
    float ps[8];
#pragma unroll
    for (int k = 0; k < 8; k++) ps[k] = 0.f;

    {
        size_t qbase = ((size_t)(i * BSZ + b) * TSEQ + t0) * DMODEL + h * HD;
#pragma unroll
        for (int kh = 0; kh < 2; kh++) {
            tile_cp_r<128>(sb + AQ_BUF + kh * 16384,         Qh + qbase + kh * 64, DMODEL, tid);
            tile_cp_r<128>(sb + AQ_BUF + 32768 + kh * 16384, Ql + qbase + kh * 64, DMODEL, tid);
        }
        CP_COMMIT();
    }
    auto stage_load = [&](int s) {
        int kh = s & 1, ch = s >> 1;
        size_t kb = ((size_t)(i * BSZ + b) * TSEQ + ch * 128) * DMODEL + h * HD + kh * 64;
        uint32_t ko = sb + AK_BUF + (s & 1) * 32768;
        tile_cp_r<128>(ko,         Kh + kb, DMODEL, tid);
        tile_cp_r<128>(ko + 16384, Kl + kb, DMODEL, tid);
        CP_COMMIT();
    };
    stage_load(0);

    size_t bh_el = ((size_t)(b * NH + h)) << 20;
    size_t rowbase = (size_t)i * PT_PLANE + bh_el + ((size_t)t0 << 10);
    const int S = 16;

    for (int s = 0; s < S; s++) {
        CP_WAIT0();
        __syncthreads();
        if (s + 1 < S) stage_load(s + 1);
        int kh = s & 1, ch = s >> 1;
        uint32_t qo = sb + AQ_BUF + kh * 16384;
        uint32_t ko = sb + AK_BUF + (s & 1) * 32768;
#pragma unroll
        for (int s16 = 0; s16 < 4; s16++) {
            int kb = s16 * 16;
            uint32_t bhf[4][2], blf[4][2];
#pragma unroll
            for (int nt = 0; nt < 4; nt++) {
                uint32_t ad = swz(ko, wn * 32 + nt * 8 + (l & 7),
                                  (kb + ((l >> 3) & 1) * 8) * 2);
                ldm2(bhf[nt], ad);
                ldm2(blf[nt], ad + 16384);
            }
#pragma unroll
            for (int mt = 0; mt < 4; mt++) {
                uint32_t ah[4], al[4];
                uint32_t aa = swz(qo, wm * 64 + mt * 16 + (l & 15),
                                  (kb + ((l >> 4) & 1) * 8) * 2);
                ldm4(ah, aa);
                ldm4(al, aa + 32768);
#pragma unroll
                for (int nt = 0; nt < 4; nt++) {
                    mma_bf(c[mt][nt], ah, bhf[nt]);
                    mma_bf(c[mt][nt], ah, blf[nt]);
                    mma_bf(c[mt][nt], al, bhf[nt]);
                }
            }
        }
        if (kh == 1) {
#pragma unroll
            for (int mt = 0; mt < 4; mt++) {
                int r0 = wm * 64 + mt * 16 + g, r1 = r0 + 8;
                float s0 = 0.f, s1 = 0.f;
#pragma unroll
                for (int nt = 0; nt < 4; nt++) {
                    int col = ch * 128 + wn * 32 + nt * 8 + q2;
                    float e0 = __expf(c[mt][nt][0] * SC);
                    float e1 = __expf(c[mt][nt][1] * SC);
                    float e2 = __expf(c[mt][nt][2] * SC);
                    float e3 = __expf(c[mt][nt][3] * SC);
                    s0 += e0 + e1; s1 += e2 + e3;
                    *reinterpret_cast<uint32_t*>(PT + rowbase + ((size_t)r0 << 10) + col) =
                        pack_h2(__float2half_rn(e0), __float2half_rn(e1));
                    *reinterpret_cast<uint32_t*>(PT + rowbase + ((size_t)r1 << 10) + col) =
                        pack_h2(__float2half_rn(e2), __float2half_rn(e3));
                }
                ps[2 * mt] += s0; ps[2 * mt + 1] += s1;
            }
#pragma unroll
            for (int a = 0; a < 4; a++)
#pragma unroll
                for (int b2 = 0; b2 < 4; b2++)
#pragma unroll
                    for (int d = 0; d < 4; d++) c[a][b2][d] = 0.f;
        }
    }

#pragma unroll
    for (int off = 1; off <= 2; off <<= 1)
#pragma unroll
        for (int k = 0; k < 8; k++)
            ps[k] += __shfl_xor_sync(0xffffffffu, ps[k], off);
    if ((l & 3) == 0) {
#pragma unroll
        for (int mt = 0; mt < 4; mt++) {
            int r0 = wm * 64 + mt * 16 + g;
            rspart[r0 * 4 + wn] = ps[2 * mt];
            rspart[(r0 + 8) * 4 + wn] = ps[2 * mt + 1];
        }
    }
    __syncthreads();
    if (tid < 128) {
        float sum = rspart[tid * 4] + rspart[tid * 4 + 1] +
                    rspart[tid * 4 + 2] + rspart[tid * 4 + 3];
        inv_out[i * (BSZ * NH * TSEQ) + (b * NH + h) * TSEQ + t0 + tid] = 0.125f / sum;
    }
}

// ===================== normalize + mean over i (vectorized 16B; P single fp16) =====================
__global__ __launch_bounds__(256) void attn_norm(
    const __half* __restrict__ PT, const float* __restrict__ inv,
    float* __restrict__ attn_out, __half* __restrict__ Ph)
{
    int r = blockIdx.x * 2 + (threadIdx.x >> 7);
    int c8 = (threadIdx.x & 127) * 8;
    size_t rowoff = ((size_t)r << 10) + c8;
    float acc[8] = {};
#pragma unroll
    for (int i = 0; i < 8; i++) {
        float iv = inv[i * (BSZ * NH * TSEQ) + r];
        uint4 hv = *reinterpret_cast<const uint4*>(PT + (size_t)i * PT_PLANE + rowoff);
        __half2* hp = reinterpret_cast<__half2*>(&hv);
#pragma unroll
        for (int j = 0; j < 4; j++) {
            float2 f = __half22float2(hp[j]);
            acc[2 * j]     += f.x * iv;
            acc[2 * j + 1] += f.y * iv;
        }
    }
    float4* ao = reinterpret_cast<float4*>(attn_out + rowoff);
    ao[0] = make_float4(acc[0], acc[1], acc[2], acc[3]);
    ao[1] = make_float4(acc[4], acc[5], acc[6], acc[7]);
    uint4 ph;
    ph.x = pack_h2(__float2half_rn(acc[0]), __float2half_rn(acc[1]));
    ph.y = pack_h2(__float2half_rn(acc[2]), __float2half_rn(acc[3]));
    ph.z = pack_h2(__float2half_rn(acc[4]), __float2half_rn(acc[5]));
    ph.w = pack_h2(__float2half_rn(acc[6]), __float2half_rn(acc[7]));
    *reinterpret_cast<uint4*>(Ph + rowoff) = ph;
}

// ===================== host =====================
extern "C" void kernel_launch(void* const* d_in, const int* in_sizes, int n_in,
                              void* d_out, int out_size) {
    (void)in_sizes; (void)n_in; (void)out_size;
    const float* query = (const float*)d_in[0];
    const float* key   = (const float*)d_in[1];
    const float* value = (const float*)d_in[2];
    const float* Wq    = (const float*)d_in[3];
    const float* Wk    = (const float*)d_in[4];
    const float* Wv    = (const float*)d_in[5];
    const float* Wo    = (const float*)d_in[6];
    float* out = (float*)d_out;
    float* out_attn = out + (size_t)BT * DMODEL;

    __nv_bfloat16* S;
    cudaGetSymbolAddress((void**)&S, g_bf);
    float* pInv;
    cudaGetSymbolAddress((void**)&pInv, g_inv);
#define AT(o) (S + (size_t)(o))
#define ATH(o) (reinterpret_cast<__half*>(S + (size_t)(o)))

    // kProj: 64x128 tile, 2 stages, 96KB -> 2 CTAs/SM (measured faster on big proj)
    // kOut:  128x128 tile, 3 stages (proven config for small GEMM)
    auto* kProj = gemm_bx3<0, 1, 1, 2, 4, 2, 4, 2>;
    auto* kOut  = gemm_bx3<0, 1, 1, 2, 4, 4, 4, 3>;
    auto* kHead = gemm_bx3<1, 0, 0, 2, 4, 4, 4, 3>;
    cudaFuncSetAttribute(kProj, cudaFuncAttributeMaxDynamicSharedMemorySize, GP_SMEM);
    cudaFuncSetAttribute(kOut,  cudaFuncAttributeMaxDynamicSharedMemorySize, GO_SMEM);
    cudaFuncSetAttribute(kHead, cudaFuncAttributeMaxDynamicSharedMemorySize, H_SMEM);
    cudaFuncSetAttribute(attn_score, cudaFuncAttributeMaxDynamicSharedMemorySize, AS_SMEM);

    dim3 blk(256);
    // 1-3: splits
    cvt_m<<<dim3(1024, 3), blk>>>(query, key, value, AT(O_QRH), 4 * MEG, 2 * MEG, 262144);
    cvt_m<<<dim3(4096, 2), blk>>>(Wq, Wk, Wq,        AT(O_WQH), 16 * MEG, 8 * MEG, 1048576);
    cvt_m<<<dim3(512, 1), blk>>>(Wv, Wv, Wv,         AT(O_WVH), 1 * MEG, 8 * MEG, 131072);

    // 4: merged Q + K + Vt projections (64x128 tiles, y=32)
    kProj<<<dim3(8, 32, 17), blk, GP_SMEM>>>(
        AT(O_QRH), AT(O_QRL), AT(O_WQH), AT(O_WQL), nullptr, AT(O_QH), AT(O_QL),
        16, DMODEL, DMODEL, DMODEL, 8,
        4 * MEG, 0LL,
        16 * MEG, (long long)DMODEL * DMODEL,
        32 * MEG, (long long)BT * DMODEL, 3);

    // 5: Wo split
    cvt_m<<<dim3(512, 1), blk>>>(Wo, Wo, Wo, AT(O_WOH), 1 * MEG, 8 * MEG, 131072);

    // 6 (profiled): scores
    attn_score<<<dim3(TSEQ / 128, NH, BSZ * NH), blk, AS_SMEM>>>(
        AT(O_QH), AT(O_QL), AT(O_KH), AT(O_KL), ATH(O_PT), pInv);

    // 7: normalize + mean over i
    attn_norm<<<BSZ * NH * TSEQ / 2, blk>>>(
        ATH(O_PT), pInv, out_attn, ATH(O_PH));

    // 8: head = P @ Vt^T (pure fp16, 1 pass)
    kHead<<<dim3(1, 8, 16), blk, H_SMEM>>>(
        AT(O_PH), AT(O_PH), AT(O_VTH), AT(O_VTH), nullptr, AT(O_HH), AT(O_HL),
        16, TSEQ, TSEQ, DMODEL, 8,
        (long long)NH * TSEQ * TSEQ, (long long)TSEQ * TSEQ,
        (long long)DMODEL * TSEQ, (long long)HD * TSEQ,
        (long long)TSEQ * DMODEL, (long long)HD, 1);

    // 9: outputs = head @ Wo^T (fp32, 128x128 tiles)
    kOut<<<dim3(8, 16, 1), blk, GO_SMEM>>>(
        AT(O_HH), AT(O_HL), AT(O_WOH), AT(O_WOL), out, nullptr, nullptr,
        16, DMODEL, DMODEL, DMODEL, 1, 0LL, 0LL, 0LL, 0LL, 0LL, 0LL, 0);
}

// round 15
// speedup vs baseline: 1.0325x; 1.0016x over previous
#include <cuda_runtime.h>
#include <cuda_bf16.h>
#include <cuda_fp16.h>
#include <cstdint>

#define BSZ 2
#define TSEQ 1024
#define DMODEL 1024
#define NH 8
#define HD 128
#define BT (BSZ * TSEQ)

// ===================== low-level helpers (sm_80+ instructions only) =====================
__device__ __forceinline__ uint32_t smem_u32(const void* p) {
    uint32_t a;
    asm("{ .reg .u64 t; cvta.to.shared.u64 t, %1; cvt.u32.u64 %0, t; }" : "=r"(a) : "l"(p));
    return a;
}
#define CP_ASYNC16(sm_addr, gptr) \
    asm volatile("cp.async.cg.shared.global [%0], [%1], 16;" :: "r"(sm_addr), "l"(gptr))
#define CP_COMMIT() asm volatile("cp.async.commit_group;")
#define CP_WAIT0()  asm volatile("cp.async.wait_group 0;")
#define CP_WAIT1()  asm volatile("cp.async.wait_group 1;")

__device__ __forceinline__ void ldm4(uint32_t* r, uint32_t a) {
    asm volatile("ldmatrix.sync.aligned.m8n8.x4.shared.b16 {%0,%1,%2,%3}, [%4];"
                 : "=r"(r[0]), "=r"(r[1]), "=r"(r[2]), "=r"(r[3]) : "r"(a));
}
__device__ __forceinline__ void ldm2(uint32_t* r, uint32_t a) {
    asm volatile("ldmatrix.sync.aligned.m8n8.x2.shared.b16 {%0,%1}, [%2];"
                 : "=r"(r[0]), "=r"(r[1]) : "r"(a));
}
__device__ __forceinline__ void mma_bf(float* c, const uint32_t* a, const uint32_t* b) {
    asm volatile(
        "mma.sync.aligned.m16n8k16.row.col.f32.bf16.bf16.f32 "
        "{%0,%1,%2,%3}, {%4,%5,%6,%7}, {%8,%9}, {%0,%1,%2,%3};"
        : "+f"(c[0]), "+f"(c[1]), "+f"(c[2]), "+f"(c[3])
        : "r"(a[0]), "r"(a[1]), "r"(a[2]), "r"(a[3]), "r"(b[0]), "r"(b[1]));
}
__device__ __forceinline__ void mma_fp(float* c, const uint32_t* a, const uint32_t* b) {
    asm volatile(
        "mma.sync.aligned.m16n8k16.row.col.f32.f16.f16.f32 "
        "{%0,%1,%2,%3}, {%4,%5,%6,%7}, {%8,%9}, {%0,%1,%2,%3};"
        : "+f"(c[0]), "+f"(c[1]), "+f"(c[2]), "+f"(c[3])
        : "r"(a[0]), "r"(a[1]), "r"(a[2]), "r"(a[3]), "r"(b[0]), "r"(b[1]));
}
template <int MMAT>
__device__ __forceinline__ void mma_any(float* c, const uint32_t* a, const uint32_t* b) {
    if constexpr (MMAT == 0) mma_bf(c, a, b);
    else mma_fp(c, a, b);
}
// tiles: rows of 64 b16 elems (128B) with 16B-granular XOR swizzle
__device__ __forceinline__ uint32_t swz(uint32_t base, int row, int kbytes) {
    uint32_t bo = (uint32_t)(row * 128 + kbytes);
    return base + (bo ^ ((bo >> 3) & 0x70));
}
template <int ROWS>
__device__ __forceinline__ void tile_cp_r(uint32_t sdst, const __nv_bfloat16* __restrict__ src,
                                          int rstride, int tid) {
#pragma unroll
    for (int it = 0; it < ROWS / 32; it++) {
        int f = tid + it * 256;
        int row = f >> 3, c8 = (f & 7) << 3;
        uint32_t bo = (uint32_t)(row * 128 + c8 * 2);
        uint32_t sw = bo ^ ((bo >> 3) & 0x70);
        CP_ASYNC16(sdst + sw, src + (size_t)row * rstride + c8);
    }
}
__device__ __forceinline__ void bsplit(float v, __nv_bfloat16& h, __nv_bfloat16& l) {
    h = __float2bfloat16(v);
    l = __float2bfloat16(v - __bfloat162float(h));
}
__device__ __forceinline__ uint32_t pack_bf2(__nv_bfloat16 a, __nv_bfloat16 b) {
    __nv_bfloat162 t; t.x = a; t.y = b;
    return *reinterpret_cast<uint32_t*>(&t);
}
__device__ __forceinline__ uint32_t pack_h2(__half a, __half b) {
    __half2 t; t.x = a; t.y = b;
    return *reinterpret_cast<uint32_t*>(&t);
}

// ===================== scratch offsets (2-byte elements) =====================
#define MEG 1048576LL
#define O_QRH (0LL)
#define O_QRL (2 * MEG)
#define O_KYH (4 * MEG)
#define O_KYL (6 * MEG)
#define O_VAH (8 * MEG)
#define O_VAL (10 * MEG)
#define O_WQH (12 * MEG)
#define O_WQL (20 * MEG)
#define O_WKH (28 * MEG)
#define O_WKL (36 * MEG)
#define O_WVH (44 * MEG)
#define O_WOH (45 * MEG)
#define O_WVL (52 * MEG)
#define O_WOL (53 * MEG)
#define O_QH  (64 * MEG)
#define O_QL  (80 * MEG)
#define O_KH  (96 * MEG)
#define O_KL  (112 * MEG)
#define O_VTH (128 * MEG)            // fp16 single Vt
#define O_PH  (132 * MEG)            // fp16 P (single)
#define O_HH  (148 * MEG)            // bf16 split head
#define O_HL  (150 * MEG)
#define O_PT  (152 * MEG)            // fp16 unnormalized exp: 8 planes x 16M
#define SCRATCH_ELEMS (280 * MEG)
__device__ __nv_bfloat16 g_bf[SCRATCH_ELEMS];
__device__ float g_inv[8 * BSZ * NH * TSEQ];   // 0.125/rowsum per (i, b, h, t)

#define PT_PLANE 16777216LL          // BSZ*NH*TSEQ*TSEQ per i

// ===================== fp32 -> bf16 hi/lo split, multi-source (8 elems/thread) =====================
__global__ __launch_bounds__(256) void cvt_m(
    const float* __restrict__ s0, const float* __restrict__ s1, const float* __restrict__ s2,
    __nv_bfloat16* __restrict__ base, long long zs, long long lo_off, int n8)
{
    int i = blockIdx.x * 256 + threadIdx.x;
    if (i >= n8) return;
    int z = blockIdx.y;
    const float* x = (z == 0) ? s0 : ((z == 1) ? s1 : s2);
    __nv_bfloat16* hi = base + (long long)z * zs;
    __nv_bfloat16* lo = hi + lo_off;
    float4 v0 = reinterpret_cast<const float4*>(x)[2 * i];
    float4 v1 = reinterpret_cast<const float4*>(x)[2 * i + 1];
    __nv_bfloat16 h[8], l[8];
    bsplit(v0.x, h[0], l[0]); bsplit(v0.y, h[1], l[1]);
    bsplit(v0.z, h[2], l[2]); bsplit(v0.w, h[3], l[3]);
    bsplit(v1.x, h[4], l[4]); bsplit(v1.y, h[5], l[5]);
    bsplit(v1.z, h[6], l[6]); bsplit(v1.w, h[7], l[7]);
    reinterpret_cast<uint4*>(hi)[i] = make_uint4(pack_bf2(h[0], h[1]), pack_bf2(h[2], h[3]),
                                                 pack_bf2(h[4], h[5]), pack_bf2(h[6], h[7]));
    reinterpret_cast<uint4*>(lo)[i] = make_uint4(pack_bf2(l[0], l[1]), pack_bf2(l[2], l[3]),
                                                 pack_bf2(l[4], l[5]), pack_bf2(l[6], l[7]));
}

// ===================== templated GEMM: C = A @ B^T =====================
// SPLITA/SPLITB: hi/lo operand splits. passes = 1 + SPLITA + SPLITB
// modes: 0 = fp32 C; 1 = bf16-split C; 2 = fp16 single transposed C; 3 = per-z (z<16: 1, else 2)
#define GP_SMEM 98304   // proj: 2 stages x 48KB (64x128) -> 2 CTAs/SM
#define GO_SMEM 196608  // out:  3 stages x 64KB (128x128)
#define H_SMEM  98304

template <int MMAT, int SPLITA, int SPLITB, int WM, int WN, int MT, int NT, int NS>
__global__ __launch_bounds__(256) void gemm_bx3(
    const __nv_bfloat16* __restrict__ Ahi, const __nv_bfloat16* __restrict__ Alo,
    const __nv_bfloat16* __restrict__ Bhi, const __nv_bfloat16* __restrict__ Blo,
    float* __restrict__ Cf, __nv_bfloat16* __restrict__ Chi, __nv_bfloat16* __restrict__ Clo,
    int kchunks, int lda, int ldb, int ldc, int zdiv,
    long long sA1, long long sA2, long long sB1, long long sB2,
    long long sC1, long long sC2, int mode)
{
    constexpr int M_TILE = WM * MT * 16;
    constexpr int N_TILE = WN * NT * 8;
    constexpr int SA = M_TILE * 128;
    constexpr int SB = N_TILE * 128;
    constexpr int NA = SPLITA ? 2 : 1;
    constexpr int NB = SPLITB ? 2 : 1;
    constexpr int STAGE = NA * SA + NB * SB;

    extern __shared__ __align__(1024) char sm[];
    int tid = threadIdx.x, wid = tid >> 5, l = tid & 31;
    int wm = wid / WN, wn = wid % WN;
    uint32_t sb = smem_u32(sm);

    int md = (mode == 3) ? ((blockIdx.z < 16) ? 1 : 2) : mode;

    long long zq = blockIdx.z / zdiv, zr = blockIdx.z % zdiv;
    const __nv_bfloat16* A0 = Ahi + zq * sA1 + zr * sA2 + (long long)blockIdx.y * M_TILE * lda;
    const __nv_bfloat16* A1 = Alo + zq * sA1 + zr * sA2 + (long long)blockIdx.y * M_TILE * lda;
    const __nv_bfloat16* B0 = Bhi + zq * sB1 + zr * sB2 + (long long)blockIdx.x * N_TILE * ldb;
    const __nv_bfloat16* B1 = Blo + zq * sB1 + zr * sB2 + (long long)blockIdx.x * N_TILE * ldb;

    float c[MT][NT][4];
#pragma unroll
    for (int a = 0; a < MT; a++)
#pragma unroll
        for (int b2 = 0; b2 < NT; b2++)
#pragma unroll
            for (int d = 0; d < 4; d++) c[a][b2][d] = 0.f;

    auto load_chunk = [&](int ck) {
        uint32_t bo = sb + (ck % NS) * STAGE;
        tile_cp_r<M_TILE>(bo, A0 + ck * 64, lda, tid);
        if constexpr (SPLITA)
            tile_cp_r<M_TILE>(bo + SA, A1 + ck * 64, lda, tid);
        tile_cp_r<N_TILE>(bo + NA * SA, B0 + ck * 64, ldb, tid);
        if constexpr (SPLITB)
            tile_cp_r<N_TILE>(bo + NA * SA + SB, B1 + ck * 64, ldb, tid);
        CP_COMMIT();
    };
#pragma unroll
    for (int p = 0; p < NS - 1; p++)
        if (p < kchunks) load_chunk(p);

    for (int ck = 0; ck < kchunks; ck++) {
        if constexpr (NS == 3) {
            if (ck + 1 < kchunks) CP_WAIT1();
            else CP_WAIT0();
        } else {
            CP_WAIT0();
        }
        __syncthreads();
        if (ck + NS - 1 < kchunks) load_chunk(ck + NS - 1);
        uint32_t bo = sb + (ck % NS) * STAGE;
#pragma unroll
        for (int s16 = 0; s16 < 4; s16++) {
            int kb = s16 * 16;
            uint32_t bh[NT][2], bl[NT][2];
#pragma unroll
            for (int nt = 0; nt < NT; nt++) {
                uint32_t ad = swz(bo + NA * SA, wn * (NT * 8) + nt * 8 + (l & 7),
                                  (kb + ((l >> 3) & 1) * 8) * 2);
                ldm2(bh[nt], ad);
                if constexpr (SPLITB) ldm2(bl[nt], ad + SB);
            }
#pragma unroll
            for (int mt = 0; mt < MT; mt++) {
                uint32_t ah[4], al[4];
                uint32_t aa = swz(bo, wm * (MT * 16) + mt * 16 + (l & 15),
                                  (kb + ((l >> 4) & 1) * 8) * 2);
                ldm4(ah, aa);
                if constexpr (SPLITA) ldm4(al, aa + SA);
#pragma unroll
                for (int nt = 0; nt < NT; nt++) {
                    mma_any<MMAT>(c[mt][nt], ah, bh[nt]);
                    if constexpr (SPLITB) mma_any<MMAT>(c[mt][nt], ah, bl[nt]);
                    if constexpr (SPLITA) mma_any<MMAT>(c[mt][nt], al, bh[nt]);
                }
            }
        }
    }

    // epilogue
    int g = l >> 2, q2 = (l & 3) * 2;
    long long czb = zq * sC1 + zr * sC2;
#pragma unroll
    for (int mt = 0; mt < MT; mt++) {
        long long m0 = (long long)blockIdx.y * M_TILE + wm * (MT * 16) + mt * 16 + g;
        long long m1 = m0 + 8;
#pragma unroll
        for (int nt = 0; nt < NT; nt++) {
            int n0 = blockIdx.x * N_TILE + wn * (NT * 8) + nt * 8 + q2;
            float* cc = c[mt][nt];
            if (md == 0) {
                *reinterpret_cast<float2*>(Cf + czb + m0 * ldc + n0) = make_float2(cc[0], cc[1]);
                *reinterpret_cast<float2*>(Cf + czb + m1 * ldc + n0) = make_float2(cc[2], cc[3]);
            } else if (md == 1) {
                __nv_bfloat16 h0, l0, h1, l1;
                bsplit(cc[0], h0, l0); bsplit(cc[1], h1, l1);
                *reinterpret_cast<uint32_t*>(Chi + czb + m0 * ldc + n0) = pack_bf2(h0, h1);
                *reinterpret_cast<uint32_t*>(Clo + czb + m0 * ldc + n0) = pack_bf2(l0, l1);
                bsplit(cc[2], h0, l0); bsplit(cc[3], h1, l1);
                *reinterpret_cast<uint32_t*>(Chi + czb + m1 * ldc + n0) = pack_bf2(h0, h1);
                *reinterpret_cast<uint32_t*>(Clo + czb + m1 * ldc + n0) = pack_bf2(l0, l1);
            } else {
                __half* ChiH = reinterpret_cast<__half*>(Chi + czb);
#pragma unroll
                for (int half = 0; half < 2; half++) {
                    long long m = half ? m1 : m0;
                    int bb = (int)(m >> 10), ss = (int)(m & 1023);
                    long long base = (long long)bb * DMODEL * TSEQ + ss;
#pragma unroll
                    for (int j = 0; j < 2; j++)
                        ChiH[base + (long long)(n0 + j) * TSEQ] = __float2half_rn(cc[half * 2 + j]);
                }
            }
        }
    }
}

// ===================== attention score pass (64-row t-tiles -> 2 CTAs/SM) =====================
// grid (16 t-tiles, 8 i, 16 bh). smem: Q 32KB | K 2x32KB | rspart 1KB = 99.3KB
#define AQ_BUF    0        // 32KB: Qh kh0|kh1 (8KB each), Ql kh0|kh1
#define AK_BUF    32768    // 2 x 32KB K double buffer
#define AS_RSPART 98304    // 64*4 fp32
#define AS_SMEM   99328

__global__ __launch_bounds__(256) void attn_score(
    const __nv_bfloat16* __restrict__ Qh, const __nv_bfloat16* __restrict__ Ql,
    const __nv_bfloat16* __restrict__ Kh, const __nv_bfloat16* __restrict__ Kl,
    __half* __restrict__ PT, float* __restrict__ inv_out)
{
    extern __shared__ __align__(1024) char sm[];
    int tid = threadIdx.x, wid = tid >> 5, l = tid & 31;
    int wm = wid >> 2, wn = wid & 3;
    uint32_t sb = smem_u32(sm);
    float* rspart = reinterpret_cast<float*>(sm + AS_RSPART);

    int i = blockIdx.y;
    int z = blockIdx.z, b = z >> 3, h = z & 7;
    int t0 = blockIdx.x * 64;
    const float SC = 0.08838834764831845f;   // 1/sqrt(128)
    int g = l >> 2, q2 = (l & 3) * 2;

    float c[2][4][4];
#pragma unroll
    for (int a = 0; a < 2; a++)
#pragma unroll
        for (int b2 = 0; b2 < 4; b2++)
#pragma unroll
            for (int d = 0; d < 4; d++) c[a][b2][d] = 0.f;
    float ps[4];
#pragma unroll
    for (int k = 0; k < 4; k++) ps[k] = 0.f;

    {
        size_t qbase = ((size_t)(i * BSZ + b) * TSEQ + t0) * DMODEL + h * HD;
#pragma unroll
        for (int kh = 0; kh < 2; kh++) {
            tile_cp_r<64>(sb + AQ_BUF + kh * 8192,         Qh + qbase + kh * 64, DMODEL, tid);
            tile_cp_r<64>(sb + AQ_BUF + 16384 + kh * 8192, Ql + qbase + kh * 64, DMODEL, tid);
        }
        CP_COMMIT();
    }
    auto stage_load = [&](int s) {
        int kh = s & 1, ch = s >> 1;
        size_t kb = ((size_t)(i * BSZ + b) * TSEQ + ch * 128) * DMODEL + h * HD + kh * 64;
        uint32_t ko = sb + AK_BUF + (s & 1) * 32768;
        tile_cp_r<128>(ko,         Kh + kb, DMODEL, tid);
        tile_cp_r<128>(ko + 16384, Kl + kb, DMODEL, tid);
        CP_COMMIT();
    };
    stage_load(0);

    size_t bh_el = ((size_t)(b * NH + h)) << 20;
    size_t rowbase = (size_t)i * PT_PLANE + bh_el + ((size_t)t0 << 10);
    const int S = 16;

    for (int s = 0; s < S; s++) {
        CP_WAIT0();
        __syncthreads();
        if (s + 1 < S) stage_load(s + 1);
        int kh = s & 1, ch = s >> 1;
        uint32_t qo = sb + AQ_BUF + kh * 8192;
        uint32_t ko = sb + AK_BUF + (s & 1) * 32768;
#pragma unroll
        for (int s16 = 0; s16 < 4; s16++) {
            int kb = s16 * 16;
            uint32_t bhf[4][2], blf[4][2];
#pragma unroll
            for (int nt = 0; nt < 4; nt++) {
                uint32_t ad = swz(ko, wn * 32 + nt * 8 + (l & 7),
                                  (kb + ((l >> 3) & 1) * 8) * 2);
                ldm2(bhf[nt], ad);
                ldm2(blf[nt], ad + 16384);
            }
#pragma unroll
            for (int mt = 0; mt < 2; mt++) {
                uint32_t ah[4], al[4];
                uint32_t aa = swz(qo, wm * 32 + mt * 16 + (l & 15),
                                  (kb + ((l >> 4) & 1) * 8) * 2);
                ldm4(ah, aa);
                ldm4(al, aa + 16384);
#pragma unroll
                for (int nt = 0; nt < 4; nt++) {
                    mma_bf(c[mt][nt], ah, bhf[nt]);
                    mma_bf(c[mt][nt], ah, blf[nt]);
                    mma_bf(c[mt][nt], al, bhf[nt]);
                }
            }
        }
        if (kh == 1) {
#pragma unroll
            for (int mt = 0; mt < 2; mt++) {
                int r0 = wm * 32 + mt * 16 + g, r1 = r0 + 8;
                float s0 = 0.f, s1 = 0.f;
#pragma unroll
                for (int nt = 0; nt < 4; nt++) {
                    int col = ch * 128 + wn * 32 + nt * 8 + q2;
                    float e0 = __expf(c[mt][nt][0] * SC);
                    float e1 = __expf(c[mt][nt][1] * SC);
                    float e2 = __expf(c[mt][nt][2] * SC);
                    float e3 = __expf(c[mt][nt][3] * SC);
                    s0 += e0 + e1; s1 += e2 + e3;
                    *reinterpret_cast<uint32_t*>(PT + rowbase + ((size_t)r0 << 10) + col) =
                        pack_h2(__float2half_rn(e0), __float2half_rn(e1));
                    *reinterpret_cast<uint32_t*>(PT + rowbase + ((size_t)r1 << 10) + col) =
                        pack_h2(__float2half_rn(e2), __float2half_rn(e3));
                }
                ps[2 * mt] += s0; ps[2 * mt + 1] += s1;
            }
#pragma unroll
            for (int a = 0; a < 2; a++)
#pragma unroll
                for (int b2 = 0; b2 < 4; b2++)
#pragma unroll
                    for (int d = 0; d < 4; d++) c[a][b2][d] = 0.f;
        }
    }

#pragma unroll
    for (int off = 1; off <= 2; off <<= 1)
#pragma unroll
        for (int k = 0; k < 4; k++)
            ps[k] += __shfl_xor_sync(0xffffffffu, ps[k], off);
    if ((l & 3) == 0) {
#pragma unroll
        for (int mt = 0; mt < 2; mt++) {
            int r0 = wm * 32 + mt * 16 + g;
            rspart[r0 * 4 + wn] = ps[2 * mt];
            rspart[(r0 + 8) * 4 + wn] = ps[2 * mt + 1];
        }
    }
    __syncthreads();
    if (tid < 64) {
        float sum = rspart[tid * 4] + rspart[tid * 4 + 1] +
                    rspart[tid * 4 + 2] + rspart[tid * 4 + 3];
        inv_out[i * (BSZ * NH * TSEQ) + (b * NH + h) * TSEQ + t0 + tid] = 0.125f / sum;
    }
}

// ===================== normalize + mean over i (vectorized 16B; P single fp16) =====================
__global__ __launch_bounds__(256) void attn_norm(
    const __half* __restrict__ PT, const float* __restrict__ inv,
    float* __restrict__ attn_out, __half* __restrict__ Ph)
{
    int r = blockIdx.x * 2 + (threadIdx.x >> 7);
    int c8 = (threadIdx.x & 127) * 8;
    size_t rowoff = ((size_t)r << 10) + c8;
    float acc[8] = {};
#pragma unroll
    for (int i = 0; i < 8; i++) {
        float iv = inv[i * (BSZ * NH * TSEQ) + r];
        uint4 hv = *reinterpret_cast<const uint4*>(PT + (size_t)i * PT_PLANE + rowoff);
        __half2* hp = reinterpret_cast<__half2*>(&hv);
#pragma unroll
        for (int j = 0; j < 4; j++) {
            float2 f = __half22float2(hp[j]);
            acc[2 * j]     += f.x * iv;
            acc[2 * j + 1] += f.y * iv;
        }
    }
    float4* ao = reinterpret_cast<float4*>(attn_out + rowoff);
    ao[0] = make_float4(acc[0], acc[1], acc[2], acc[3]);
    ao[1] = make_float4(acc[4], acc[5], acc[6], acc[7]);
    uint4 ph;
    ph.x = pack_h2(__float2half_rn(acc[0]), __float2half_rn(acc[1]));
    ph.y = pack_h2(__float2half_rn(acc[2]), __float2half_rn(acc[3]));
    ph.z = pack_h2(__float2half_rn(acc[4]), __float2half_rn(acc[5]));
    ph.w = pack_h2(__float2half_rn(acc[6]), __float2half_rn(acc[7]));
    *reinterpret_cast<uint4*>(Ph + rowoff) = ph;
}

// ===================== host =====================
extern "C" void kernel_launch(void* const* d_in, const int* in_sizes, int n_in,
                              void* d_out, int out_size) {
    (void)in_sizes; (void)n_in; (void)out_size;
    const float* query = (const float*)d_in[0];
    const float* key   = (const float*)d_in[1];
    const float* value = (const float*)d_in[2];
    const float* Wq    = (const float*)d_in[3];
    const float* Wk    = (const float*)d_in[4];
    const float* Wv    = (const float*)d_in[5];
    const float* Wo    = (const float*)d_in[6];
    float* out = (float*)d_out;
    float* out_attn = out + (size_t)BT * DMODEL;

    __nv_bfloat16* S;
    cudaGetSymbolAddress((void**)&S, g_bf);
    float* pInv;
    cudaGetSymbolAddress((void**)&pInv, g_inv);
#define AT(o) (S + (size_t)(o))
#define ATH(o) (reinterpret_cast<__half*>(S + (size_t)(o)))

    auto* kProj = gemm_bx3<0, 1, 1, 2, 4, 2, 4, 2>;
    auto* kOut  = gemm_bx3<0, 1, 1, 2, 4, 4, 4, 3>;
    auto* kHead = gemm_bx3<1, 0, 0, 2, 4, 4, 4, 3>;
    cudaFuncSetAttribute(kProj, cudaFuncAttributeMaxDynamicSharedMemorySize, GP_SMEM);
    cudaFuncSetAttribute(kOut,  cudaFuncAttributeMaxDynamicSharedMemorySize, GO_SMEM);
    cudaFuncSetAttribute(kHead, cudaFuncAttributeMaxDynamicSharedMemorySize, H_SMEM);
    cudaFuncSetAttribute(attn_score, cudaFuncAttributeMaxDynamicSharedMemorySize, AS_SMEM);

    dim3 blk(256);
    // 1-3: splits
    cvt_m<<<dim3(1024, 3), blk>>>(query, key, value, AT(O_QRH), 4 * MEG, 2 * MEG, 262144);
    cvt_m<<<dim3(4096, 2), blk>>>(Wq, Wk, Wq,        AT(O_WQH), 16 * MEG, 8 * MEG, 1048576);
    cvt_m<<<dim3(512, 1), blk>>>(Wv, Wv, Wv,         AT(O_WVH), 1 * MEG, 8 * MEG, 131072);

    // 4: merged Q + K + Vt projections (64x128 tiles, y=32)
    kProj<<<dim3(8, 32, 17), blk, GP_SMEM>>>(
        AT(O_QRH), AT(O_QRL), AT(O_WQH), AT(O_WQL), nullptr, AT(O_QH), AT(O_QL),
        16, DMODEL, DMODEL, DMODEL, 8,
        4 * MEG, 0LL,
        16 * MEG, (long long)DMODEL * DMODEL,
        32 * MEG, (long long)BT * DMODEL, 3);

    // 5: Wo split
    cvt_m<<<dim3(512, 1), blk>>>(Wo, Wo, Wo, AT(O_WOH), 1 * MEG, 8 * MEG, 131072);

    // 6 (profiled): scores — 64-row t-tiles, 2048 CTAs, 2 CTAs/SM
    attn_score<<<dim3(TSEQ / 64, NH, BSZ * NH), blk, AS_SMEM>>>(
        AT(O_QH), AT(O_QL), AT(O_KH), AT(O_KL), ATH(O_PT), pInv);

    // 7: normalize + mean over i
    attn_norm<<<BSZ * NH * TSEQ / 2, blk>>>(
        ATH(O_PT), pInv, out_attn, ATH(O_PH));

    // 8: head = P @ Vt^T (pure fp16, 1 pass)
    kHead<<<dim3(1, 8, 16), blk, H_SMEM>>>(
        AT(O_PH), AT(O_PH), AT(O_VTH), AT(O_VTH), nullptr, AT(O_HH), AT(O_HL),
        16, TSEQ, TSEQ, DMODEL, 8,
        (long long)NH * TSEQ * TSEQ, (long long)TSEQ * TSEQ,
        (long long)DMODEL * TSEQ, (long long)HD * TSEQ,
        (long long)TSEQ * DMODEL, (long long)HD, 1);

    // 9: outputs = head @ Wo^T (fp32, 128x128 tiles)
    kOut<<<dim3(8, 16, 1), blk, GO_SMEM>>>(
        AT(O_HH), AT(O_HL), AT(O_WOH), AT(O_WOL), out, nullptr, nullptr,
        16, DMODEL, DMODEL, DMODEL, 1, 0LL, 0LL, 0LL, 0LL, 0LL, 0LL, 0);
}